// round 2
// baseline (speedup 1.0000x reference)
#include <cuda_runtime.h>
#include <math.h>

// FilterInterpolationModule: adaptive 4x4 filter + bilinear warp.
// The 16 taps x 4 bilinear corners collapse to a 5x5 patch with an
// effective per-pixel 5x5 weight kernel (exact reorder of the reference sum).
//
// R2: shared-memory tile for input1 gathers. Flow ~N(0,1), so a margin-8
// tile covers the 5x5 window for (essentially) all pixels; per-thread
// in-tile test falls back to global gathers for outliers. Border clamping
// is applied at tile-load time, matching the reference's per-sample clip.

namespace {
constexpr int H  = 544;
constexpr int W  = 960;
constexpr int C  = 3;
constexpr int FS = 4;
constexpr int HW = H * W;

constexpr int BX = 32;              // pixels per block in x
constexpr int BY = 16;              // pixels per block in y
constexpr int M  = 8;               // flow margin covered by tile
constexpr int TR = BY + 2 * M + 4;  // 36 tile rows
constexpr int TC = BX + 2 * M + 4;  // 52 tile cols
constexpr int NTHREADS = BX * BY;   // 512
}

__global__ __launch_bounds__(NTHREADS) void filter_interp_kernel(
    const float* __restrict__ input1,   // [B, C, H, W]
    const float* __restrict__ input2,   // [B, 2, H, W]  (fx, fy)
    const float* __restrict__ input3,   // [B, 16, H, W]
    float* __restrict__ out)            // [B, C, H, W]
{
    __shared__ float tile[C][TR][TC];

    const int tid = threadIdx.x;
    const int tx  = tid & (BX - 1);
    const int ty  = tid >> 5;           // BX == 32
    const int x0  = blockIdx.x * BX;
    const int y0  = blockIdx.y * BY;
    const int b   = blockIdx.z;

    const int rowbase = y0 - (M + 1);
    const int colbase = x0 - (M + 1);

    // ---- cooperative tile load (border-clamped) ----
    const float* imgb = input1 + (size_t)(b * C) * HW;
    {
        constexpr int planeElems = TR * TC;   // 1872
        float* tflat = &tile[0][0][0];
        for (int idx = tid; idx < C * planeElems; idx += NTHREADS) {
            const int ch  = idx / planeElems;
            const int rem = idx - ch * planeElems;
            const int r   = rem / TC;
            const int c   = rem - r * TC;
            int gr = min(max(rowbase + r, 0), H - 1);
            int gc = min(max(colbase + c, 0), W - 1);
            tflat[idx] = imgb[ch * HW + gr * W + gc];
        }
    }
    __syncthreads();

    const int x = x0 + tx;
    const int y = y0 + ty;
    const int pix = y * W + x;

    const float fx = input2[(b * 2 + 0) * HW + pix];
    const float fy = input2[(b * 2 + 1) * HW + pix];

    const float x2 = (float)x + fx;
    const float y2 = (float)y + fy;

    const bool mask =
        (x2 >= 0.0f) && (y2 >= 0.0f) &&
        (x2 <= (float)(W - 1)) && (y2 <= (float)(H - 1)) &&
        (fabsf(fx) < (float)W * 0.5f) && (fabsf(fy) < (float)H * 0.5f);

    float* outp = out + (size_t)(b * C) * HW + pix;

    if (!mask) {
#pragma unroll
        for (int c = 0; c < C; c++) outp[c * HW] = 0.0f;
        return;
    }

    const float x2c = fminf(fmaxf(x2, 0.0f), (float)(W - 1));
    const float y2c = fminf(fmaxf(y2, 0.0f), (float)(H - 1));
    const int ix = (int)floorf(x2c);
    const int iy = (int)floorf(y2c);
    const float alpha = x2c - (float)ix;
    const float beta  = y2c - (float)iy;
    const int ixL = ix - 1;   // ix + 1 - fs/2
    const int iyT = iy - 1;

    const float wa = (1.0f - alpha) * (1.0f - beta);
    const float wb = alpha * (1.0f - beta);
    const float wc = (1.0f - alpha) * beta;
    const float wd = alpha * beta;

    // Effective 5x5 weights from 4x4 filter taps x bilinear corners.
    float eff[5][5];
#pragma unroll
    for (int j = 0; j < 5; j++)
#pragma unroll
        for (int i = 0; i < 5; i++) eff[j][i] = 0.0f;

    const float* w3p = input3 + (size_t)(b * FS * FS) * HW + pix;
#pragma unroll
    for (int j = 0; j < FS; j++) {
#pragma unroll
        for (int i = 0; i < FS; i++) {
            const float w = w3p[(j * FS + i) * HW];
            eff[j][i]         += wa * w;
            eff[j][i + 1]     += wb * w;
            eff[j + 1][i]     += wc * w;
            eff[j + 1][i + 1] += wd * w;
        }
    }

    const int rL = iyT - rowbase;
    const int cL = ixL - colbase;
    const bool inTile = (rL >= 0) & (cL >= 0) & (rL <= TR - 5) & (cL <= TC - 5);

    if (inTile) {
        // ---- fast path: 5x5 gathers from smem (conflict-free-ish) ----
#pragma unroll
        for (int c = 0; c < C; c++) {
            const float* tp = &tile[c][rL][cL];
            float acc = 0.0f;
#pragma unroll
            for (int j = 0; j < 5; j++) {
#pragma unroll
                for (int i = 0; i < 5; i++) {
                    acc += eff[j][i] * tp[j * TC + i];
                }
            }
            outp[c * HW] = acc;
        }
    } else {
        // ---- fallback: global gathers with per-sample clamp ----
        int rowOff[5];
        int colIdx[5];
#pragma unroll
        for (int k = 0; k < 5; k++) {
            int r = iyT + k;
            r = min(max(r, 0), H - 1);
            rowOff[k] = r * W;
            int cc = ixL + k;
            cc = min(max(cc, 0), W - 1);
            colIdx[k] = cc;
        }
#pragma unroll
        for (int c = 0; c < C; c++) {
            const float* imgc = imgb + c * HW;
            float acc = 0.0f;
#pragma unroll
            for (int j = 0; j < 5; j++) {
#pragma unroll
                for (int i = 0; i < 5; i++) {
                    acc += eff[j][i] * __ldg(imgc + rowOff[j] + colIdx[i]);
                }
            }
            outp[c * HW] = acc;
        }
    }
}

extern "C" void kernel_launch(void* const* d_in, const int* in_sizes, int n_in,
                              void* d_out, int out_size) {
    const float* input1 = (const float*)d_in[0];
    const float* input2 = (const float*)d_in[1];
    const float* input3 = (const float*)d_in[2];
    float* out = (float*)d_out;

    const int B = in_sizes[1] / (2 * HW);

    dim3 block(NTHREADS);
    dim3 grid(W / BX, H / BY, B);
    filter_interp_kernel<<<grid, block>>>(input1, input2, input3, out);
}

// round 3
// speedup vs baseline: 1.0856x; 1.0856x over previous
#include <cuda_runtime.h>
#include <math.h>

// FilterInterpolationModule: adaptive 4x4 filter + bilinear warp.
// 16 taps x 4 bilinear corners collapse to an effective per-pixel 5x5 kernel.
//
// R3: vectorized gathers. The 5 needed columns [ixL, ixL+4] live inside the
// aligned 8-float window [ixL & ~3, +8); load it as 2x float4 per row per
// channel (30 LDG.128 vs 75 LDG.32). The misalignment o = ixL & 3 is folded
// into an 8-wide shifted weight row built with indicator FMAs (branch-free,
// no dynamic register indexing). Boundary threads fall back to the scalar
// per-sample-clamped path (exactly the reference semantics).

namespace {
constexpr int H  = 544;
constexpr int W  = 960;
constexpr int C  = 3;
constexpr int FS = 4;
constexpr int HW = H * W;
}

__global__ __launch_bounds__(256) void filter_interp_kernel(
    const float* __restrict__ input1,   // [B, C, H, W]
    const float* __restrict__ input2,   // [B, 2, H, W]  (fx, fy)
    const float* __restrict__ input3,   // [B, 16, H, W]
    float* __restrict__ out)            // [B, C, H, W]
{
    const int pix = blockIdx.x * blockDim.x + threadIdx.x;
    const int b   = blockIdx.y;
    if (pix >= HW) return;

    const int y = pix / W;
    const int x = pix - y * W;

    const float fx = __ldg(input2 + (b * 2 + 0) * HW + pix);
    const float fy = __ldg(input2 + (b * 2 + 1) * HW + pix);

    const float x2 = (float)x + fx;
    const float y2 = (float)y + fy;

    const bool mask =
        (x2 >= 0.0f) && (y2 >= 0.0f) &&
        (x2 <= (float)(W - 1)) && (y2 <= (float)(H - 1)) &&
        (fabsf(fx) < (float)W * 0.5f) && (fabsf(fy) < (float)H * 0.5f);

    float* outp = out + (size_t)(b * C) * HW + pix;

    if (!mask) {
#pragma unroll
        for (int c = 0; c < C; c++) outp[c * HW] = 0.0f;
        return;
    }

    const float x2c = fminf(fmaxf(x2, 0.0f), (float)(W - 1));
    const float y2c = fminf(fmaxf(y2, 0.0f), (float)(H - 1));
    const int ix = (int)floorf(x2c);
    const int iy = (int)floorf(y2c);
    const float alpha = x2c - (float)ix;
    const float beta  = y2c - (float)iy;
    const int ixL = ix - 1;   // ix + 1 - fs/2
    const int iyT = iy - 1;

    const float wa = (1.0f - alpha) * (1.0f - beta);
    const float wb = alpha * (1.0f - beta);
    const float wc = (1.0f - alpha) * beta;
    const float wd = alpha * beta;

    // Effective 5x5 weights from 4x4 filter taps x bilinear corners.
    float eff[5][5];
#pragma unroll
    for (int j = 0; j < 5; j++)
#pragma unroll
        for (int i = 0; i < 5; i++) eff[j][i] = 0.0f;

    const float* w3p = input3 + (size_t)(b * FS * FS) * HW + pix;
#pragma unroll
    for (int j = 0; j < FS; j++) {
#pragma unroll
        for (int i = 0; i < FS; i++) {
            const float w = __ldg(w3p + (j * FS + i) * HW);
            eff[j][i]         += wa * w;
            eff[j][i + 1]     += wb * w;
            eff[j + 1][i]     += wc * w;
            eff[j + 1][i + 1] += wd * w;
        }
    }

    // Clamped row offsets (row clamping is free in both paths).
    int rowOff[5];
#pragma unroll
    for (int k = 0; k < 5; k++) {
        int r = iyT + k;
        r = min(max(r, 0), H - 1);
        rowOff[k] = r * W;
    }

    const float* imgb = input1 + (size_t)(b * C) * HW;

    const int ixL4 = ixL & ~3;          // aligned window start
    const int o    = ixL - ixL4;        // 0..3 misalignment
    const bool fastX = (ixL >= 0) && (ixL4 + 8 <= W);

    if (fastX) {
        // Indicator weights for the shift o (branch-free, uniform code path).
        const float m0 = (o == 0) ? 1.0f : 0.0f;
        const float m1 = (o == 1) ? 1.0f : 0.0f;
        const float m2 = (o == 2) ? 1.0f : 0.0f;
        const float m3 = (o == 3) ? 1.0f : 0.0f;

        float acc0 = 0.0f, acc1 = 0.0f, acc2 = 0.0f;

#pragma unroll
        for (int j = 0; j < 5; j++) {
            // e8[k] = eff[j][k - o] for 0 <= k-o <= 4, else 0.
            float e8[8];
#pragma unroll
            for (int k = 0; k < 8; k++) {
                float v = 0.0f;
                if (k - 0 >= 0 && k - 0 <= 4) v = fmaf(m0, eff[j][k - 0], v);
                if (k - 1 >= 0 && k - 1 <= 4) v = fmaf(m1, eff[j][k - 1], v);
                if (k - 2 >= 0 && k - 2 <= 4) v = fmaf(m2, eff[j][k - 2], v);
                if (k - 3 >= 0 && k - 3 <= 4) v = fmaf(m3, eff[j][k - 3], v);
                e8[k] = v;
            }

            const float* rp = imgb + rowOff[j] + ixL4;
            {
                const float4 a = *(const float4*)(rp);
                const float4 d = *(const float4*)(rp + 4);
                acc0 = fmaf(e8[0], a.x, acc0); acc0 = fmaf(e8[1], a.y, acc0);
                acc0 = fmaf(e8[2], a.z, acc0); acc0 = fmaf(e8[3], a.w, acc0);
                acc0 = fmaf(e8[4], d.x, acc0); acc0 = fmaf(e8[5], d.y, acc0);
                acc0 = fmaf(e8[6], d.z, acc0); acc0 = fmaf(e8[7], d.w, acc0);
            }
            {
                const float4 a = *(const float4*)(rp + HW);
                const float4 d = *(const float4*)(rp + HW + 4);
                acc1 = fmaf(e8[0], a.x, acc1); acc1 = fmaf(e8[1], a.y, acc1);
                acc1 = fmaf(e8[2], a.z, acc1); acc1 = fmaf(e8[3], a.w, acc1);
                acc1 = fmaf(e8[4], d.x, acc1); acc1 = fmaf(e8[5], d.y, acc1);
                acc1 = fmaf(e8[6], d.z, acc1); acc1 = fmaf(e8[7], d.w, acc1);
            }
            {
                const float4 a = *(const float4*)(rp + 2 * HW);
                const float4 d = *(const float4*)(rp + 2 * HW + 4);
                acc2 = fmaf(e8[0], a.x, acc2); acc2 = fmaf(e8[1], a.y, acc2);
                acc2 = fmaf(e8[2], a.z, acc2); acc2 = fmaf(e8[3], a.w, acc2);
                acc2 = fmaf(e8[4], d.x, acc2); acc2 = fmaf(e8[5], d.y, acc2);
                acc2 = fmaf(e8[6], d.z, acc2); acc2 = fmaf(e8[7], d.w, acc2);
            }
        }
        outp[0 * HW] = acc0;
        outp[1 * HW] = acc1;
        outp[2 * HW] = acc2;
    } else {
        // Slow path: per-sample column clamp (boundary threads only).
        int colIdx[5];
#pragma unroll
        for (int k = 0; k < 5; k++) {
            int cc = ixL + k;
            cc = min(max(cc, 0), W - 1);
            colIdx[k] = cc;
        }
#pragma unroll
        for (int c = 0; c < C; c++) {
            const float* imgc = imgb + c * HW;
            float acc = 0.0f;
#pragma unroll
            for (int j = 0; j < 5; j++) {
#pragma unroll
                for (int i = 0; i < 5; i++) {
                    acc += eff[j][i] * __ldg(imgc + rowOff[j] + colIdx[i]);
                }
            }
            outp[c * HW] = acc;
        }
    }
}

extern "C" void kernel_launch(void* const* d_in, const int* in_sizes, int n_in,
                              void* d_out, int out_size) {
    const float* input1 = (const float*)d_in[0];
    const float* input2 = (const float*)d_in[1];
    const float* input3 = (const float*)d_in[2];
    float* out = (float*)d_out;

    const int B = in_sizes[1] / (2 * HW);

    dim3 block(256);
    dim3 grid((HW + 255) / 256, B);
    filter_interp_kernel<<<grid, block>>>(input1, input2, input3, out);
}

// round 4
// speedup vs baseline: 1.5091x; 1.3902x over previous
#include <cuda_runtime.h>
#include <math.h>

// FilterInterpolationModule: adaptive 4x4 filter + bilinear warp.
// 16 taps x 4 bilinear corners collapse to an effective per-pixel 5x5 kernel.
//
// R4: scalar gathers (byte-optimal for the L1 return crossbar: 25 samples x
// 3 channels x 4B = minimum traffic). Streaming eff-row construction: patch
// row j only needs filter-tap rows j-1 and j, so we keep 2 tap rows live
// instead of the full 5x5 eff array -> ~20 fewer live registers ->
// 6 blocks/SM (75% occupancy) to push L1 from 82% toward its ceiling.

namespace {
constexpr int H  = 544;
constexpr int W  = 960;
constexpr int C  = 3;
constexpr int FS = 4;
constexpr int HW = H * W;
}

__global__ __launch_bounds__(256, 6) void filter_interp_kernel(
    const float* __restrict__ input1,   // [B, C, H, W]
    const float* __restrict__ input2,   // [B, 2, H, W]  (fx, fy)
    const float* __restrict__ input3,   // [B, 16, H, W]
    float* __restrict__ out)            // [B, C, H, W]
{
    const int pix = blockIdx.x * blockDim.x + threadIdx.x;
    const int b   = blockIdx.y;
    if (pix >= HW) return;

    const int y = pix / W;
    const int x = pix - y * W;

    const float fx = __ldg(input2 + (b * 2 + 0) * HW + pix);
    const float fy = __ldg(input2 + (b * 2 + 1) * HW + pix);

    const float x2 = (float)x + fx;
    const float y2 = (float)y + fy;

    const bool mask =
        (x2 >= 0.0f) && (y2 >= 0.0f) &&
        (x2 <= (float)(W - 1)) && (y2 <= (float)(H - 1)) &&
        (fabsf(fx) < (float)W * 0.5f) && (fabsf(fy) < (float)H * 0.5f);

    float* outp = out + (size_t)(b * C) * HW + pix;

    if (!mask) {
#pragma unroll
        for (int c = 0; c < C; c++) outp[c * HW] = 0.0f;
        return;
    }

    const float x2c = fminf(fmaxf(x2, 0.0f), (float)(W - 1));
    const float y2c = fminf(fmaxf(y2, 0.0f), (float)(H - 1));
    const int ix = (int)floorf(x2c);
    const int iy = (int)floorf(y2c);
    const float alpha = x2c - (float)ix;
    const float beta  = y2c - (float)iy;
    const int ixL = ix - 1;   // ix + 1 - fs/2
    const int iyT = iy - 1;

    const float wa = (1.0f - alpha) * (1.0f - beta);
    const float wb = alpha * (1.0f - beta);
    const float wc = (1.0f - alpha) * beta;
    const float wd = alpha * beta;

    // Clamped column indices (uniform path; matches reference per-sample clip).
    int col[5];
#pragma unroll
    for (int k = 0; k < 5; k++) {
        col[k] = min(max(ixL + k, 0), W - 1);
    }

    const float* imgb = input1 + (size_t)(b * C) * HW;
    const float* w3p  = input3 + (size_t)(b * FS * FS) * HW + pix;

    float acc0 = 0.0f, acc1 = 0.0f, acc2 = 0.0f;

    // Streaming over the 5 patch rows. Patch row j draws on filter-tap
    // rows j-1 (prev) and j (cur):
    //   eff[j][i] = wa*cur[i] + wb*cur[i-1] + wc*prev[i] + wd*prev[i-1]
    // with out-of-range tap indices contributing 0.
    float prevRow[4] = {0.0f, 0.0f, 0.0f, 0.0f};

#pragma unroll
    for (int j = 0; j < 5; j++) {
        float curRow[4];
        if (j < FS) {
#pragma unroll
            for (int i = 0; i < FS; i++)
                curRow[i] = __ldg(w3p + (j * FS + i) * HW);
        } else {
#pragma unroll
            for (int i = 0; i < FS; i++) curRow[i] = 0.0f;
        }

        float e[5];
        e[0] = wa * curRow[0] + wc * prevRow[0];
        e[1] = fmaf(wa, curRow[1], fmaf(wb, curRow[0],
               fmaf(wc, prevRow[1], wd * prevRow[0])));
        e[2] = fmaf(wa, curRow[2], fmaf(wb, curRow[1],
               fmaf(wc, prevRow[2], wd * prevRow[1])));
        e[3] = fmaf(wa, curRow[3], fmaf(wb, curRow[2],
               fmaf(wc, prevRow[3], wd * prevRow[2])));
        e[4] = fmaf(wb, curRow[3], wd * prevRow[3]);

        const int r = min(max(iyT + j, 0), H - 1);
        const float* rp = imgb + r * W;

#pragma unroll
        for (int i = 0; i < 5; i++) {
            const float s0 = __ldg(rp + col[i]);
            const float s1 = __ldg(rp + HW + col[i]);
            const float s2 = __ldg(rp + 2 * HW + col[i]);
            acc0 = fmaf(e[i], s0, acc0);
            acc1 = fmaf(e[i], s1, acc1);
            acc2 = fmaf(e[i], s2, acc2);
        }

#pragma unroll
        for (int i = 0; i < FS; i++) prevRow[i] = curRow[i];
    }

    outp[0 * HW] = acc0;
    outp[1 * HW] = acc1;
    outp[2 * HW] = acc2;
}

extern "C" void kernel_launch(void* const* d_in, const int* in_sizes, int n_in,
                              void* d_out, int out_size) {
    const float* input1 = (const float*)d_in[0];
    const float* input2 = (const float*)d_in[1];
    const float* input3 = (const float*)d_in[2];
    float* out = (float*)d_out;

    const int B = in_sizes[1] / (2 * HW);

    dim3 block(256);
    dim3 grid((HW + 255) / 256, B);
    filter_interp_kernel<<<grid, block>>>(input1, input2, input3, out);
}

// round 5
// speedup vs baseline: 1.6208x; 1.0740x over previous
#include <cuda_runtime.h>
#include <math.h>

// FilterInterpolationModule: adaptive 4x4 filter + bilinear warp.
// 16 taps x 4 bilinear corners collapse to an effective per-pixel 5x5 kernel.
//
// R5 = R1 structure (fully materialized eff[5][5], then per-channel
// front-batched blocks of 25 independent scalar gathers = max MLP for the
// L1 wavefront pipe) + 6 blocks/SM occupancy (launch_bounds cap 42 regs).
// Single uniform clamped path (no fast/slow branch).

namespace {
constexpr int H  = 544;
constexpr int W  = 960;
constexpr int C  = 3;
constexpr int FS = 4;
constexpr int HW = H * W;
}

__global__ __launch_bounds__(256, 6) void filter_interp_kernel(
    const float* __restrict__ input1,   // [B, C, H, W]
    const float* __restrict__ input2,   // [B, 2, H, W]  (fx, fy)
    const float* __restrict__ input3,   // [B, 16, H, W]
    float* __restrict__ out)            // [B, C, H, W]
{
    const int pix = blockIdx.x * blockDim.x + threadIdx.x;
    const int b   = blockIdx.y;
    if (pix >= HW) return;

    const int y = pix / W;
    const int x = pix - y * W;

    const float fx = __ldg(input2 + (b * 2 + 0) * HW + pix);
    const float fy = __ldg(input2 + (b * 2 + 1) * HW + pix);

    const float x2 = (float)x + fx;
    const float y2 = (float)y + fy;

    const bool mask =
        (x2 >= 0.0f) && (y2 >= 0.0f) &&
        (x2 <= (float)(W - 1)) && (y2 <= (float)(H - 1)) &&
        (fabsf(fx) < (float)W * 0.5f) && (fabsf(fy) < (float)H * 0.5f);

    float* outp = out + (size_t)(b * C) * HW + pix;

    if (!mask) {
#pragma unroll
        for (int c = 0; c < C; c++) outp[c * HW] = 0.0f;
        return;
    }

    const float x2c = fminf(fmaxf(x2, 0.0f), (float)(W - 1));
    const float y2c = fminf(fmaxf(y2, 0.0f), (float)(H - 1));
    const int ix = (int)floorf(x2c);
    const int iy = (int)floorf(y2c);
    const float alpha = x2c - (float)ix;
    const float beta  = y2c - (float)iy;
    const int ixL = ix - 1;   // ix + 1 - fs/2
    const int iyT = iy - 1;

    const float wa = (1.0f - alpha) * (1.0f - beta);
    const float wb = alpha * (1.0f - beta);
    const float wc = (1.0f - alpha) * beta;
    const float wd = alpha * beta;

    // Effective 5x5 weights from 4x4 filter taps x bilinear corners.
    float eff[5][5];
#pragma unroll
    for (int j = 0; j < 5; j++)
#pragma unroll
        for (int i = 0; i < 5; i++) eff[j][i] = 0.0f;

    const float* w3p = input3 + (size_t)(b * FS * FS) * HW + pix;
#pragma unroll
    for (int j = 0; j < FS; j++) {
#pragma unroll
        for (int i = 0; i < FS; i++) {
            const float w = __ldg(w3p + (j * FS + i) * HW);
            eff[j][i]         += wa * w;
            eff[j][i + 1]     += wb * w;
            eff[j + 1][i]     += wc * w;
            eff[j + 1][i + 1] += wd * w;
        }
    }

    // Clamped patch indices (matches reference's per-tap clipping exactly).
    int rowOff[5];
    int colIdx[5];
#pragma unroll
    for (int k = 0; k < 5; k++) {
        int r = iyT + k;
        r = min(max(r, 0), H - 1);
        rowOff[k] = r * W;
        int cc = ixL + k;
        cc = min(max(cc, 0), W - 1);
        colIdx[k] = cc;
    }

    // Per-channel front-batched gather blocks: 25 independent scalar LDGs
    // per channel, all addresses resolved before the block starts.
    const float* imgb = input1 + (size_t)(b * C) * HW;
#pragma unroll
    for (int c = 0; c < C; c++) {
        const float* imgc = imgb + c * HW;
        float acc = 0.0f;
#pragma unroll
        for (int j = 0; j < 5; j++) {
#pragma unroll
            for (int i = 0; i < 5; i++) {
                acc = fmaf(eff[j][i], __ldg(imgc + rowOff[j] + colIdx[i]), acc);
            }
        }
        outp[c * HW] = acc;
    }
}

extern "C" void kernel_launch(void* const* d_in, const int* in_sizes, int n_in,
                              void* d_out, int out_size) {
    const float* input1 = (const float*)d_in[0];
    const float* input2 = (const float*)d_in[1];
    const float* input3 = (const float*)d_in[2];
    float* out = (float*)d_out;

    const int B = in_sizes[1] / (2 * HW);

    dim3 block(256);
    dim3 grid((HW + 255) / 256, B);
    filter_interp_kernel<<<grid, block>>>(input1, input2, input3, out);
}